// round 7
// baseline (speedup 1.0000x reference)
#include <cuda_runtime.h>

// ---------------- problem constants ----------------
#define WSZ 21
#define KK  43
#define HH  128
#define WW  128
#define BB  2
#define LPOW4 0.4f                       // pow applied to d^2
#define C1T 20.0f
#define C2T 10.0f
#define LOG2E 1.4426950408889634f
#define KC2 (-50.0f * LOG2E)             // log2-scale color sigma
#define KS2 (-(1.0f/98.0f) * LOG2E)      // log2-scale space sigma

// ---------------- tiling ----------------
#define TX 32
#define TY 8
#define PAD 22                            // WSZ + 1 (Sobel ring for halo masks)
#define PITCH (TX + 2*PAD)                // 76
#define ROWS2 (TY + 2*PAD)                // 52
#define PLANE2 (ROWS2*PITCH)              // 3952
#define NTHREADS 256
#define NSPLIT 6
#define GXD (WW/TX)                       // 4
#define GYD (HH/TY)                       // 16
#define NPART (GXD*GYD*BB*NSPLIT)         // 768

// mask region: rows [22,50], cols [1,74]
#define MROWS 29
#define MCOLS 74

__device__ double       g_part[NPART];
__device__ unsigned int g_tick;

__device__ __forceinline__ int refl(int i, int n) {
    if (i < 0)  i = -i;
    if (i >= n) i = 2*n - 2 - i;
    return i;
}
__device__ __forceinline__ float ex2f(float x) {
    float y; asm("ex2.approx.ftz.f32 %0, %1;" : "=f"(y) : "f"(x)); return y;
}
__device__ __forceinline__ float lg2f(float x) {
    float y; asm("lg2.approx.ftz.f32 %0, %1;" : "=f"(y) : "f"(x)); return y;
}

// symmetric pair: both endpoints in-bounds, counted once; weights (mi+mj) / (2-mi-mj)
#define PAIR_ITER(DX) { \
    const int ii = rbase + (DX); \
    float4 A = SA[ii]; float2 Bv = SB[ii]; \
    float mj = (float)M8[ii]; \
    float d0 = cs0 - A.x, d1 = cs1 - A.y, d2 = cs2 - A.z; \
    float t0 = d0*d0, t1 = d1*d1, t2 = d2*d2; \
    float dd = (t0 + t1) + t2; \
    float e0 = co0 - A.w, e1 = co1 - Bv.x, e2 = co2 - Bv.y; \
    float ee = fmaf(e0, e0, fmaf(e1, e1, e2*e2)); \
    float Wl = KC2 * ee; \
    float P = (ex2f(fmaf(LPOW4, lg2f(t0), Wl)) \
             + ex2f(fmaf(LPOW4, lg2f(t1), Wl))) \
             + ex2f(fmaf(LPOW4, lg2f(t2), Wl)); \
    if ((unsigned)(px + (DX)) < 128u) { \
        float u = mAi + mj; \
        rowA = fmaf(u, wsx[(DX) + WSZ] * dd, rowA); \
        accB = fmaf(2.0f - u, P, accB); \
    } }

// directed OOB term: padded tile already holds reflected values; weight mi only (factored out)
#define DIR_ITER(DX, PRED) { \
    const int ii = rbase + (DX); \
    float4 A = SA[ii]; float2 Bv = SB[ii]; \
    float d0 = cs0 - A.x, d1 = cs1 - A.y, d2 = cs2 - A.z; \
    float t0 = d0*d0, t1 = d1*d1, t2 = d2*d2; \
    float dd = (t0 + t1) + t2; \
    float e0 = co0 - A.w, e1 = co1 - Bv.x, e2 = co2 - Bv.y; \
    float ee = fmaf(e0, e0, fmaf(e1, e1, e2*e2)); \
    float Wl = KC2 * ee; \
    float P = (ex2f(fmaf(LPOW4, lg2f(t0), Wl)) \
             + ex2f(fmaf(LPOW4, lg2f(t1), Wl))) \
             + ex2f(fmaf(LPOW4, lg2f(t2), Wl)); \
    if (PRED) { \
        rowA2 = fmaf(wsx[(DX) + WSZ], dd, rowA2); \
        accBo += P; \
    } }

__global__ void __launch_bounds__(NTHREADS, 2)
loss_kernel(const float* __restrict__ orig, const float* __restrict__ smth,
            float* __restrict__ out) {
    extern __shared__ float smem[];
    float4*        SA = (float4*)smem;                          // (s0,s1,s2,o0)
    float2*        SB = (float2*)(smem + PLANE2*4);             // (o1,o2)
    unsigned char* M8 = (unsigned char*)(smem + PLANE2*6);      // mask 0/1

    __shared__ float  wsx[KK];
    __shared__ double wsum[NTHREADS/32];
    __shared__ double red[NTHREADS];
    __shared__ int    s_last;

    const int t     = threadIdx.x;
    const int bz    = blockIdx.z;
    const int b     = bz / NSPLIT;
    const int chunk = bz - b*NSPLIT;
    const int bx    = blockIdx.x;
    const int by    = blockIdx.y;

    const int x0 = bx*TX - PAD;
    const int y0 = by*TY - PAD;

    const size_t cs = (size_t)HH*WW;
    const float* __restrict__ sb = smth + (size_t)b*3*cs;
    const float* __restrict__ ob = orig + (size_t)b*3*cs;

    // ---- load reflect-padded tile (AoS packed) ----
    for (int i = t; i < PLANE2; i += NTHREADS) {
        int r = i / PITCH;
        int c = i - r*PITCH;
        int gh = refl(y0 + r, HH);
        int gw = refl(x0 + c, WW);
        int g  = gh*WW + gw;
        SA[i] = make_float4(sb[g], sb[g+cs], sb[g+2*cs], ob[g]);
        SB[i] = make_float2(ob[g+cs], ob[g+2*cs]);
    }
    if (t < KK) {
        float dx = (float)(t - WSZ);
        wsx[t] = ex2f(KS2 * dx * dx);
    }
    __syncthreads();

    // ---- mask plane: Sobel over padded tile (exact for every in-bounds pixel) ----
    for (int idx = t; idx < MROWS*MCOLS; idx += NTHREADS) {
        int r = PAD + idx / MCOLS;        // 22..50
        int c = 1 + idx - (idx / MCOLS)*MCOLS;  // 1..74
        int q = r*PITCH + c;
        float4 a00 = SA[q-PITCH-1], a01 = SA[q-PITCH], a02 = SA[q-PITCH+1];
        float4 a10 = SA[q-1],                          a12 = SA[q+1];
        float4 a20 = SA[q+PITCH-1], a21 = SA[q+PITCH], a22 = SA[q+PITCH+1];
        float2 b00 = SB[q-PITCH-1], b01 = SB[q-PITCH], b02 = SB[q-PITCH+1];
        float2 b10 = SB[q-1],                          b12 = SB[q+1];
        float2 b20 = SB[q+PITCH-1], b21 = SB[q+PITCH], b22 = SB[q+PITCH+1];
        float es, eo, gx, gy;
        gx = (a02.x-a00.x) + 2.f*(a12.x-a10.x) + (a22.x-a20.x);
        gy = (a20.x-a00.x) + 2.f*(a21.x-a01.x) + (a22.x-a02.x);
        es = sqrtf(gx*gx + gy*gy);
        gx = (a02.y-a00.y) + 2.f*(a12.y-a10.y) + (a22.y-a20.y);
        gy = (a20.y-a00.y) + 2.f*(a21.y-a01.y) + (a22.y-a02.y);
        es += sqrtf(gx*gx + gy*gy);
        gx = (a02.z-a00.z) + 2.f*(a12.z-a10.z) + (a22.z-a20.z);
        gy = (a20.z-a00.z) + 2.f*(a21.z-a01.z) + (a22.z-a02.z);
        es += sqrtf(gx*gx + gy*gy);
        gx = (a02.w-a00.w) + 2.f*(a12.w-a10.w) + (a22.w-a20.w);
        gy = (a20.w-a00.w) + 2.f*(a21.w-a01.w) + (a22.w-a02.w);
        eo = sqrtf(gx*gx + gy*gy);
        gx = (b02.x-b00.x) + 2.f*(b12.x-b10.x) + (b22.x-b20.x);
        gy = (b20.x-b00.x) + 2.f*(b21.x-b01.x) + (b22.x-b02.x);
        eo += sqrtf(gx*gx + gy*gy);
        gx = (b02.y-b00.y) + 2.f*(b12.y-b10.y) + (b22.y-b20.y);
        gy = (b20.y-b00.y) + 2.f*(b21.y-b01.y) + (b22.y-b02.y);
        eo += sqrtf(gx*gx + gy*gy);
        M8[q] = ((eo < C1T) && (es - eo > C2T)) ? 1 : 0;
    }
    __syncthreads();

    const int tx = t & 31;
    const int ty = t >> 5;
    const int px = bx*TX + tx;
    const int py = by*TY + ty;
    const int ci = (ty + PAD)*PITCH + (tx + PAD);

    float4 CA = SA[ci]; float2 CB = SB[ci];
    const float cs0 = CA.x, cs1 = CA.y, cs2 = CA.z;
    const float co0 = CA.w, co1 = CB.x, co2 = CB.y;
    const float mAi = (float)M8[ci];

    float accA = 0.f;    // pass1 A-part ((mi+mj)·ws·d², wy-folded)
    float accB = 0.f;    // pass1 B-part ((2-mi-mj)·wr·|d|^0.8)
    float accAo = 0.f;   // pass2 A-part (unit weight, wy-folded; × mAi at end)
    float accBo = 0.f;   // pass2 B-part (unit weight; × (1-mAi) at end)

    // ======== PASS 1: symmetric pairs, upper-half offsets {dy>0} ∪ {dy=0,dx>0} ========
    for (int dy = chunk; dy <= WSZ; dy += NSPLIT) {
        if (py + dy > 127) continue;                 // j row OOB -> pass2 territory
        const float wy = ex2f(KS2 * (float)(dy*dy));
        const int rbase = (ty + PAD + dy)*PITCH + (tx + PAD);
        float rowA = 0.f;
        if (dy == 0) {
#pragma unroll
            for (int dx = 1; dx <= WSZ; dx++) PAIR_ITER(dx)
        } else {
#pragma unroll
            for (int dx = -WSZ; dx <= WSZ; dx++) PAIR_ITER(dx)
        }
        accA = fmaf(wy, rowA, accA);
    }

    // ======== PASS 2: OOB-offset directed terms (tile pad = reflected values) ========
    for (int dy2 = chunk - WSZ; dy2 <= WSZ; dy2 += NSPLIT) {
        const unsigned jy = (unsigned)(py + dy2);
        const float wy2 = ex2f(KS2 * (float)(dy2*dy2));
        const int rbase = (ty + PAD + dy2)*PITCH + (tx + PAD);
        float rowA2 = 0.f;
        if (jy >= 128u) {                            // whole row OOB in y
#pragma unroll
            for (int dx = -WSZ; dx <= WSZ; dx++) DIR_ITER(dx, true)
        } else if (bx == 0) {                        // left x-stub
#pragma unroll
            for (int dx = -WSZ; dx <= -1; dx++) DIR_ITER(dx, (px + dx) < 0)
        } else if (bx == GXD-1) {                    // right x-stub
#pragma unroll
            for (int dx = 1; dx <= WSZ; dx++) DIR_ITER(dx, (px + dx) > 127)
        } else {
            continue;
        }
        accAo = fmaf(wy2, rowA2, accAo);
    }

    float tot = accA + accB + mAi*accAo + (1.0f - mAi)*accBo;

    // ---- deterministic block reduction ----
#pragma unroll
    for (int o = 16; o > 0; o >>= 1)
        tot += __shfl_down_sync(0xffffffffu, tot, o);
    if ((t & 31) == 0) wsum[t >> 5] = (double)tot;
    __syncthreads();

    const int bid = blockIdx.x + GXD*(blockIdx.y + GYD*blockIdx.z);
    if (t == 0) {
        double s = 0.0;
#pragma unroll
        for (int i = 0; i < NTHREADS/32; i++) s += wsum[i];
        g_part[bid] = s;
        __threadfence();
        unsigned r = atomicAdd(&g_tick, 1u);
        s_last = (r == NPART - 1);
    }
    __syncthreads();

    if (s_last) {
        __threadfence();
        double s = 0.0;
#pragma unroll
        for (int k = 0; k < NPART/NTHREADS; k++)
            s += g_part[t + k*NTHREADS];
        red[t] = s;
        __syncthreads();
#pragma unroll
        for (int o = NTHREADS/2; o > 0; o >>= 1) {
            if (t < o) red[t] += red[t + o];
            __syncthreads();
        }
        if (t == 0) {
            out[0] = (float)(red[0] / (double)(BB*HH*WW));
            g_tick = 0;
        }
    }
}

extern "C" void kernel_launch(void* const* d_in, const int* in_sizes, int n_in,
                              void* d_out, int out_size) {
    const float* orig = (const float*)d_in[0];
    const float* smth = (const float*)d_in[1];
    float* out = (float*)d_out;

    const int smem_bytes = PLANE2*24 + PLANE2;   // SA(16B)+SB(8B)+mask(1B) = 98800
    cudaFuncSetAttribute(loss_kernel,
                         cudaFuncAttributeMaxDynamicSharedMemorySize, smem_bytes);

    loss_kernel<<<dim3(GXD, GYD, BB*NSPLIT), NTHREADS, smem_bytes>>>(orig, smth, out);
}